// round 1
// baseline (speedup 1.0000x reference)
#include <cuda_runtime.h>
#include <math.h>
#include <stdint.h>

#define S_LEN 4096
#define D_MODEL 1024
#define NUM_HEADS 16
#define D_K 64

// ---------------- scratch (no allocs allowed) ----------------
__device__ float g_Q[S_LEN * D_MODEL];
__device__ float g_K[S_LEN * D_MODEL];
__device__ float g_V[S_LEN * D_MODEL];
__device__ float g_AT[S_LEN * D_MODEL];

// ---------------- GEMM: C[m,n] = sum_k A[m,k] * B[n,k]  (NT) ----------------
#define BM 128
#define BN 128
#define BK 16

__global__ __launch_bounds__(256)
void gemm_nt_kernel(const float* __restrict__ A, const float* __restrict__ B,
                    float* __restrict__ C, int M, int N, int K) {
    __shared__ float As[BK][BM + 4];
    __shared__ float Bs[BK][BN + 4];
    const int tid = threadIdx.x;
    const int m0 = blockIdx.y * BM;
    const int n0 = blockIdx.x * BN;
    const int ty = tid >> 4;   // 0..15
    const int tx = tid & 15;   // 0..15

    float acc[8][8];
#pragma unroll
    for (int i = 0; i < 8; i++)
#pragma unroll
        for (int j = 0; j < 8; j++) acc[i][j] = 0.f;

    for (int k0 = 0; k0 < K; k0 += BK) {
        // Load A tile: 128 rows x 16 cols => 512 float4, 2 per thread
#pragma unroll
        for (int it = 0; it < 2; it++) {
            int idx = tid + it * 256;          // float4 index
            int row = idx >> 2;                // 4 float4 per row (BK=16)
            int c4  = idx & 3;
            float4 v = *reinterpret_cast<const float4*>(
                &A[(size_t)(m0 + row) * K + k0 + c4 * 4]);
            As[c4 * 4 + 0][row] = v.x;
            As[c4 * 4 + 1][row] = v.y;
            As[c4 * 4 + 2][row] = v.z;
            As[c4 * 4 + 3][row] = v.w;
        }
#pragma unroll
        for (int it = 0; it < 2; it++) {
            int idx = tid + it * 256;
            int row = idx >> 2;
            int c4  = idx & 3;
            float4 v = *reinterpret_cast<const float4*>(
                &B[(size_t)(n0 + row) * K + k0 + c4 * 4]);
            Bs[c4 * 4 + 0][row] = v.x;
            Bs[c4 * 4 + 1][row] = v.y;
            Bs[c4 * 4 + 2][row] = v.z;
            Bs[c4 * 4 + 3][row] = v.w;
        }
        __syncthreads();

#pragma unroll
        for (int kk = 0; kk < BK; kk++) {
            float a[8], b[8];
            float4 a0 = *reinterpret_cast<const float4*>(&As[kk][ty * 8]);
            float4 a1 = *reinterpret_cast<const float4*>(&As[kk][ty * 8 + 4]);
            float4 b0 = *reinterpret_cast<const float4*>(&Bs[kk][tx * 8]);
            float4 b1 = *reinterpret_cast<const float4*>(&Bs[kk][tx * 8 + 4]);
            a[0]=a0.x; a[1]=a0.y; a[2]=a0.z; a[3]=a0.w;
            a[4]=a1.x; a[5]=a1.y; a[6]=a1.z; a[7]=a1.w;
            b[0]=b0.x; b[1]=b0.y; b[2]=b0.z; b[3]=b0.w;
            b[4]=b1.x; b[5]=b1.y; b[6]=b1.z; b[7]=b1.w;
#pragma unroll
            for (int i = 0; i < 8; i++)
#pragma unroll
                for (int j = 0; j < 8; j++)
                    acc[i][j] = fmaf(a[i], b[j], acc[i][j]);
        }
        __syncthreads();
    }

#pragma unroll
    for (int i = 0; i < 8; i++) {
        int m = m0 + ty * 8 + i;
#pragma unroll
        for (int j = 0; j < 8; j += 4) {
            float4 v = make_float4(acc[i][j], acc[i][j+1], acc[i][j+2], acc[i][j+3]);
            *reinterpret_cast<float4*>(&C[(size_t)m * N + n0 + tx * 8 + j]) = v;
        }
    }
}

// ---------------- RoPE (interleaved), applied to Q and K in place ----------------
__global__ void rope_kernel(float* __restrict__ Q, float* __restrict__ K,
                            const int* __restrict__ pos) {
    int idx = blockIdx.x * blockDim.x + threadIdx.x;  // over S*H*32
    if (idx >= S_LEN * NUM_HEADS * (D_K / 2)) return;
    int pair = idx & 31;
    int h    = (idx >> 5) & (NUM_HEADS - 1);
    int s    = idx >> 9;

    float p = (float)pos[s];
    // inv_freq = theta^{-(2*pair)/dk}
    float expo = (float)(2 * pair) / (float)D_K;
    float inv_freq = powf(10000.0f, -expo);
    float ang = p * inv_freq;
    float c, sn;
    sincosf(ang, &sn, &c);

    size_t base = (size_t)s * D_MODEL + h * D_K + pair * 2;
    float q1 = Q[base], q2 = Q[base + 1];
    Q[base]     = q1 * c - q2 * sn;
    Q[base + 1] = q1 * sn + q2 * c;
    float k1 = K[base], k2 = K[base + 1];
    K[base]     = k1 * c - k2 * sn;
    K[base + 1] = k1 * sn + k2 * c;
}

// ---------------- Flash attention, causal, fp32 ----------------
// Q/K/V layout: [S, D_MODEL], head h at columns [h*64, h*64+64)
#define FBM 64
#define FBN 64
#define KP 72   // smem row pitch (floats): 72*4 bytes = 288, 16B aligned

__global__ __launch_bounds__(256)
void attn_kernel(const float* __restrict__ Q, const float* __restrict__ K,
                 const float* __restrict__ V, float* __restrict__ O) {
    extern __shared__ float sm[];
    float* Ks = sm;                  // [64][KP]
    float* Vs = sm + FBN * KP;       // [64][KP]
    float* Sc = sm + 2 * FBN * KP;   // [64][KP]

    const int h  = blockIdx.y;
    const int q0 = blockIdx.x * FBM;
    const int tid = threadIdx.x;
    const int row = tid >> 2;   // 0..63
    const int sub = tid & 3;    // 0..3
    const int qi  = q0 + row;
    const float scale = 0.125f; // 1/sqrt(64)

    // load this thread's q segment (16 floats)
    float q[16];
    {
        const float* qp = Q + (size_t)qi * D_MODEL + h * D_K + sub * 16;
#pragma unroll
        for (int i = 0; i < 16; i += 4) {
            float4 v = *reinterpret_cast<const float4*>(&qp[i]);
            q[i] = v.x; q[i+1] = v.y; q[i+2] = v.z; q[i+3] = v.w;
        }
    }

    float acc[16];
#pragma unroll
    for (int i = 0; i < 16; i++) acc[i] = 0.f;
    float m = -1e30f, l = 0.f;

    const int kend = q0 + FBM;  // causal: kv tiles up to and including the diagonal tile
    for (int kv0 = 0; kv0 < kend; kv0 += FBN) {
        // load K/V tiles: 64x64 each => 1024 float4 per tile, 4 per thread
#pragma unroll
        for (int it = 0; it < 4; it++) {
            int idx = tid + it * 256;     // float4 index 0..1023
            int r  = idx >> 4;            // 16 float4 per row
            int c4 = idx & 15;
            float4 kv = *reinterpret_cast<const float4*>(
                &K[(size_t)(kv0 + r) * D_MODEL + h * D_K + c4 * 4]);
            *reinterpret_cast<float4*>(&Ks[r * KP + c4 * 4]) = kv;
            float4 vv = *reinterpret_cast<const float4*>(
                &V[(size_t)(kv0 + r) * D_MODEL + h * D_K + c4 * 4]);
            *reinterpret_cast<float4*>(&Vs[r * KP + c4 * 4]) = vv;
        }
        __syncthreads();

        // scores: 4 threads per q-row, each does partial dot over its 16 dims
#pragma unroll 4
        for (int c = 0; c < FBN; c++) {
            const float* kr = &Ks[c * KP + sub * 16];
            float p = 0.f;
#pragma unroll
            for (int i = 0; i < 16; i++) p = fmaf(q[i], kr[i], p);
            p += __shfl_xor_sync(0xffffffffu, p, 1);
            p += __shfl_xor_sync(0xffffffffu, p, 2);
            if (sub == 0)
                Sc[row * KP + c] = (kv0 + c <= qi) ? p * scale : -1e30f;
        }
        __syncwarp();

        // online softmax + PV
        float mt = m;
#pragma unroll 8
        for (int c = 0; c < FBN; c++) mt = fmaxf(mt, Sc[row * KP + c]);
        float alpha = __expf(m - mt) ; // m,mt finite after first valid tile
        // use precise expf to be safe on accuracy:
        alpha = expf(m - mt);
        l *= alpha;
#pragma unroll
        for (int i = 0; i < 16; i++) acc[i] *= alpha;

#pragma unroll 2
        for (int c = 0; c < FBN; c++) {
            float p = expf(Sc[row * KP + c] - mt);
            l += p;
            const float* vr = &Vs[c * KP + sub * 16];
#pragma unroll
            for (int i = 0; i < 16; i++) acc[i] = fmaf(p, vr[i], acc[i]);
        }
        m = mt;
        __syncthreads();
    }

    float invl = 1.0f / l;
    float* op = O + (size_t)qi * D_MODEL + h * D_K + sub * 16;
#pragma unroll
    for (int i = 0; i < 16; i += 4) {
        float4 v = make_float4(acc[i]*invl, acc[i+1]*invl, acc[i+2]*invl, acc[i+3]*invl);
        *reinterpret_cast<float4*>(&op[i]) = v;
    }
}

// ---------------- launcher ----------------
extern "C" void kernel_launch(void* const* d_in, const int* in_sizes, int n_in,
                              void* d_out, int out_size) {
    const float* x  = (const float*)d_in[0];
    const float* Wq = (const float*)d_in[1];
    const float* Wk = (const float*)d_in[2];
    const float* Wv = (const float*)d_in[3];
    const float* Wo = (const float*)d_in[4];
    const int*  pos = (const int*)d_in[5];
    float* out = (float*)d_out;

    float *Qp, *Kp, *Vp, *Ap;
    cudaGetSymbolAddress((void**)&Qp, g_Q);
    cudaGetSymbolAddress((void**)&Kp, g_K);
    cudaGetSymbolAddress((void**)&Vp, g_V);
    cudaGetSymbolAddress((void**)&Ap, g_AT);

    dim3 ggrid(D_MODEL / BN, S_LEN / BM);   // (8, 32)
    gemm_nt_kernel<<<ggrid, 256>>>(x, Wq, Qp, S_LEN, D_MODEL, D_MODEL);
    gemm_nt_kernel<<<ggrid, 256>>>(x, Wk, Kp, S_LEN, D_MODEL, D_MODEL);
    gemm_nt_kernel<<<ggrid, 256>>>(x, Wv, Vp, S_LEN, D_MODEL, D_MODEL);

    int rope_threads = S_LEN * NUM_HEADS * (D_K / 2);
    rope_kernel<<<(rope_threads + 255) / 256, 256>>>(Qp, Kp, pos);

    int attn_smem = 3 * FBN * KP * sizeof(float);  // 55296 B
    static bool attr_set = false;
    cudaFuncSetAttribute(attn_kernel, cudaFuncAttributeMaxDynamicSharedMemorySize, attn_smem);
    (void)attr_set;
    dim3 agrid(S_LEN / FBM, NUM_HEADS);            // (64, 16)
    attn_kernel<<<agrid, 256, attn_smem>>>(Qp, Kp, Vp, Ap);

    gemm_nt_kernel<<<ggrid, 256>>>(Ap, Wo, out, S_LEN, D_MODEL, D_MODEL);
}

// round 2
// speedup vs baseline: 4.4340x; 4.4340x over previous
#include <cuda_runtime.h>
#include <math.h>
#include <stdint.h>

#define S_LEN 4096
#define D_MODEL 1024
#define NUM_HEADS 16
#define D_K 64

// ---------------- scratch (no allocs allowed) ----------------
__device__ float g_Q[S_LEN * D_MODEL];
__device__ float g_K[S_LEN * D_MODEL];
__device__ float g_V[S_LEN * D_MODEL];
__device__ float g_AT[S_LEN * D_MODEL];

// ---------------- helpers ----------------
__device__ __forceinline__ float tf32r(float x) {
    uint32_t u;
    asm("cvt.rna.tf32.f32 %0, %1;" : "=r"(u) : "f"(x));
    return __uint_as_float(u);
}

__device__ __forceinline__ void mma_tf32(float* d, const uint32_t* a, uint32_t b0, uint32_t b1) {
    asm volatile(
        "mma.sync.aligned.m16n8k8.row.col.f32.tf32.tf32.f32 "
        "{%0,%1,%2,%3}, {%4,%5,%6,%7}, {%8,%9}, {%0,%1,%2,%3};"
        : "+f"(d[0]), "+f"(d[1]), "+f"(d[2]), "+f"(d[3])
        : "r"(a[0]), "r"(a[1]), "r"(a[2]), "r"(a[3]), "r"(b0), "r"(b1));
}

// ---------------- 3xTF32 GEMM: C[m,n] = sum_k A[m,k]*B[n,k] (NT) ----------------
#define GBM 128
#define GBN 128
#define GBK 16
#define G_STR 20   // 20 mod 32 => g*20 spans {0,20,8,28,16,4,24,12}: conflict-free frags

__global__ __launch_bounds__(256)
void gemm3x_kernel(const float* __restrict__ A, const float* __restrict__ B,
                   float* __restrict__ C, int M, int N, int K) {
    __shared__ float Ash[GBM * G_STR];
    __shared__ float Asl[GBM * G_STR];
    __shared__ float Bsh[GBN * G_STR];
    __shared__ float Bsl[GBN * G_STR];

    const int tid = threadIdx.x;
    const int m0 = blockIdx.y * GBM;
    const int n0 = blockIdx.x * GBN;
    const int w = tid >> 5, lane = tid & 31;
    const int g = lane >> 2, t4 = lane & 3;
    const int wm = w >> 1, wn = w & 1;     // 4x2 warp grid, warp tile 32x64

    float acc[2][8][4];
#pragma unroll
    for (int i = 0; i < 2; i++)
#pragma unroll
        for (int j = 0; j < 8; j++)
#pragma unroll
            for (int e = 0; e < 4; e++) acc[i][j][e] = 0.f;

    for (int k0 = 0; k0 < K; k0 += GBK) {
#pragma unroll
        for (int it = 0; it < 2; it++) {
            int idx = tid + it * 256;        // float4 index: 512 per tile
            int row = idx >> 2;
            int c4  = idx & 3;
            float4 va = *reinterpret_cast<const float4*>(&A[(size_t)(m0 + row) * K + k0 + c4 * 4]);
            float4 hi, lo;
            hi.x = tf32r(va.x); lo.x = tf32r(va.x - hi.x);
            hi.y = tf32r(va.y); lo.y = tf32r(va.y - hi.y);
            hi.z = tf32r(va.z); lo.z = tf32r(va.z - hi.z);
            hi.w = tf32r(va.w); lo.w = tf32r(va.w - hi.w);
            *reinterpret_cast<float4*>(&Ash[row * G_STR + c4 * 4]) = hi;
            *reinterpret_cast<float4*>(&Asl[row * G_STR + c4 * 4]) = lo;
            float4 vb = *reinterpret_cast<const float4*>(&B[(size_t)(n0 + row) * K + k0 + c4 * 4]);
            hi.x = tf32r(vb.x); lo.x = tf32r(vb.x - hi.x);
            hi.y = tf32r(vb.y); lo.y = tf32r(vb.y - hi.y);
            hi.z = tf32r(vb.z); lo.z = tf32r(vb.z - hi.z);
            hi.w = tf32r(vb.w); lo.w = tf32r(vb.w - hi.w);
            *reinterpret_cast<float4*>(&Bsh[row * G_STR + c4 * 4]) = hi;
            *reinterpret_cast<float4*>(&Bsl[row * G_STR + c4 * 4]) = lo;
        }
        __syncthreads();

#pragma unroll
        for (int kk = 0; kk < GBK; kk += 8) {
            uint32_t ah[2][4], al[2][4];
#pragma unroll
            for (int i = 0; i < 2; i++) {
                int r = (wm * 32 + i * 16 + g) * G_STR + kk + t4;
                ah[i][0] = __float_as_uint(Ash[r]);
                ah[i][1] = __float_as_uint(Ash[r + 8 * G_STR]);
                ah[i][2] = __float_as_uint(Ash[r + 4]);
                ah[i][3] = __float_as_uint(Ash[r + 8 * G_STR + 4]);
                al[i][0] = __float_as_uint(Asl[r]);
                al[i][1] = __float_as_uint(Asl[r + 8 * G_STR]);
                al[i][2] = __float_as_uint(Asl[r + 4]);
                al[i][3] = __float_as_uint(Asl[r + 8 * G_STR + 4]);
            }
#pragma unroll
            for (int j = 0; j < 8; j++) {
                int rb = (wn * 64 + j * 8 + g) * G_STR + kk + t4;
                uint32_t bh0 = __float_as_uint(Bsh[rb]);
                uint32_t bh1 = __float_as_uint(Bsh[rb + 4]);
                uint32_t bl0 = __float_as_uint(Bsl[rb]);
                uint32_t bl1 = __float_as_uint(Bsl[rb + 4]);
#pragma unroll
                for (int i = 0; i < 2; i++) {
                    mma_tf32(acc[i][j], ah[i], bh0, bh1);
                    mma_tf32(acc[i][j], ah[i], bl0, bl1);
                    mma_tf32(acc[i][j], al[i], bh0, bh1);
                }
            }
        }
        __syncthreads();
    }

#pragma unroll
    for (int i = 0; i < 2; i++)
#pragma unroll
        for (int j = 0; j < 8; j++) {
            int r = m0 + wm * 32 + i * 16 + g;
            int c = n0 + wn * 64 + j * 8 + 2 * t4;
            float2 v0 = make_float2(acc[i][j][0], acc[i][j][1]);
            float2 v1 = make_float2(acc[i][j][2], acc[i][j][3]);
            *reinterpret_cast<float2*>(&C[(size_t)r * N + c]) = v0;
            *reinterpret_cast<float2*>(&C[(size_t)(r + 8) * N + c]) = v1;
        }
}

// ---------------- RoPE (interleaved), Q and K in place ----------------
__global__ void rope_kernel(float* __restrict__ Q, float* __restrict__ K,
                            const int* __restrict__ pos) {
    int idx = blockIdx.x * blockDim.x + threadIdx.x;
    if (idx >= S_LEN * NUM_HEADS * (D_K / 2)) return;
    int pair = idx & 31;
    int h    = (idx >> 5) & (NUM_HEADS - 1);
    int s    = idx >> 9;

    float p = (float)pos[s];
    float expo = (float)(2 * pair) / (float)D_K;
    float inv_freq = powf(10000.0f, -expo);
    float ang = p * inv_freq;
    float c, sn;
    sincosf(ang, &sn, &c);

    size_t base = (size_t)s * D_MODEL + h * D_K + pair * 2;
    float q1 = Q[base], q2 = Q[base + 1];
    Q[base]     = q1 * c - q2 * sn;
    Q[base + 1] = q1 * sn + q2 * c;
    float k1 = K[base], k2 = K[base + 1];
    K[base]     = k1 * c - k2 * sn;
    K[base + 1] = k1 * sn + k2 * c;
}

// ---------------- Flash attention with tf32 mma ----------------
// CTA: 128 q-rows x one head, 8 warps (16 q-rows each). KV tiles of 64.
// QK uses 3xTF32, PV uses 1x tf32.
#define AQ 128
#define AK 64
#define KS_STR 68   // 68 mod 32 = 4 -> g*4 distinct, +t4 conflict-free
#define V_STR  72   // 72 mod 32 = 8 -> t4*8 distinct, +g conflict-free
#define PS_STR 68

#define ATTN_SMEM ((2 * AK * KS_STR + AK * V_STR + AQ * PS_STR) * 4)

__global__ __launch_bounds__(256)
void attn_mma_kernel(const float* __restrict__ Q, const float* __restrict__ K,
                     const float* __restrict__ V, float* __restrict__ O) {
    extern __shared__ float sm[];
    float* Ksh = sm;                       // [64][68] tf32 hi
    float* Ksl = Ksh + AK * KS_STR;        // [64][68] tf32 lo
    float* Vs  = Ksl + AK * KS_STR;        // [64][72] tf32
    float* Ps  = Vs + AK * V_STR;          // [128][68] tf32 P

    const int h   = blockIdx.y;
    const int q0  = (gridDim.x - 1 - blockIdx.x) * AQ;  // big-work CTAs first
    const int tid = threadIdx.x;
    const int w = tid >> 5, lane = tid & 31;
    const int g = lane >> 2, t4 = lane & 3;
    const int wrow = q0 + w * 16;

    // Q fragments (hi/lo), scaled by 1/sqrt(dk)=0.125
    uint32_t qh[8][4], ql[8][4];
    {
        const float* qb = Q + (size_t)wrow * D_MODEL + h * D_K;
#pragma unroll
        for (int kc = 0; kc < 8; kc++) {
            int c0 = kc * 8 + t4;
            float v0 = qb[(size_t)g * D_MODEL + c0] * 0.125f;
            float v1 = qb[(size_t)(g + 8) * D_MODEL + c0] * 0.125f;
            float v2 = qb[(size_t)g * D_MODEL + c0 + 4] * 0.125f;
            float v3 = qb[(size_t)(g + 8) * D_MODEL + c0 + 4] * 0.125f;
            float hv;
            hv = tf32r(v0); qh[kc][0] = __float_as_uint(hv); ql[kc][0] = __float_as_uint(tf32r(v0 - hv));
            hv = tf32r(v1); qh[kc][1] = __float_as_uint(hv); ql[kc][1] = __float_as_uint(tf32r(v1 - hv));
            hv = tf32r(v2); qh[kc][2] = __float_as_uint(hv); ql[kc][2] = __float_as_uint(tf32r(v2 - hv));
            hv = tf32r(v3); qh[kc][3] = __float_as_uint(hv); ql[kc][3] = __float_as_uint(tf32r(v3 - hv));
        }
    }

    float o[8][4];
#pragma unroll
    for (int j = 0; j < 8; j++)
#pragma unroll
        for (int e = 0; e < 4; e++) o[j][e] = 0.f;
    float m_a = -1e30f, m_b = -1e30f, l_a = 0.f, l_b = 0.f;

    for (int kv0 = 0; kv0 < q0 + AQ; kv0 += AK) {
        // cooperative K/V tile load + tf32 split
#pragma unroll
        for (int it = 0; it < 4; it++) {
            int idx = tid + it * 256;     // 1024 float4 per tile
            int r = idx >> 4, c4 = idx & 15;
            float4 kv4 = *reinterpret_cast<const float4*>(
                &K[(size_t)(kv0 + r) * D_MODEL + h * D_K + c4 * 4]);
            float4 hi, lo;
            hi.x = tf32r(kv4.x); lo.x = tf32r(kv4.x - hi.x);
            hi.y = tf32r(kv4.y); lo.y = tf32r(kv4.y - hi.y);
            hi.z = tf32r(kv4.z); lo.z = tf32r(kv4.z - hi.z);
            hi.w = tf32r(kv4.w); lo.w = tf32r(kv4.w - hi.w);
            *reinterpret_cast<float4*>(&Ksh[r * KS_STR + c4 * 4]) = hi;
            *reinterpret_cast<float4*>(&Ksl[r * KS_STR + c4 * 4]) = lo;
            float4 vv = *reinterpret_cast<const float4*>(
                &V[(size_t)(kv0 + r) * D_MODEL + h * D_K + c4 * 4]);
            float4 vh;
            vh.x = tf32r(vv.x); vh.y = tf32r(vv.y); vh.z = tf32r(vv.z); vh.w = tf32r(vv.w);
            *reinterpret_cast<float4*>(&Vs[r * V_STR + c4 * 4]) = vh;
        }
        __syncthreads();

        if (kv0 <= wrow + 15) {   // this warp has unmasked work in this tile
            // S = Q K^T (3xTF32)
            float s[8][4];
#pragma unroll
            for (int j = 0; j < 8; j++)
#pragma unroll
                for (int e = 0; e < 4; e++) s[j][e] = 0.f;

#pragma unroll
            for (int kc = 0; kc < 8; kc++) {
#pragma unroll
                for (int j = 0; j < 8; j++) {
                    int rb = (j * 8 + g) * KS_STR + kc * 8 + t4;
                    uint32_t bh0 = __float_as_uint(Ksh[rb]);
                    uint32_t bh1 = __float_as_uint(Ksh[rb + 4]);
                    uint32_t bl0 = __float_as_uint(Ksl[rb]);
                    uint32_t bl1 = __float_as_uint(Ksl[rb + 4]);
                    mma_tf32(s[j], qh[kc], bh0, bh1);
                    mma_tf32(s[j], qh[kc], bl0, bl1);
                    mma_tf32(s[j], ql[kc], bh0, bh1);
                }
            }

            // causal mask (diagonal tiles only)
            if (kv0 + AK - 1 > wrow) {
#pragma unroll
                for (int j = 0; j < 8; j++) {
                    int col = kv0 + j * 8 + 2 * t4;
                    int ra = wrow + g, rb2 = wrow + g + 8;
                    if (col > ra)      s[j][0] = -1e30f;
                    if (col + 1 > ra)  s[j][1] = -1e30f;
                    if (col > rb2)     s[j][2] = -1e30f;
                    if (col + 1 > rb2) s[j][3] = -1e30f;
                }
            }

            // online softmax
            float mx_a = -1e30f, mx_b = -1e30f;
#pragma unroll
            for (int j = 0; j < 8; j++) {
                mx_a = fmaxf(mx_a, fmaxf(s[j][0], s[j][1]));
                mx_b = fmaxf(mx_b, fmaxf(s[j][2], s[j][3]));
            }
            mx_a = fmaxf(mx_a, __shfl_xor_sync(0xffffffffu, mx_a, 1));
            mx_a = fmaxf(mx_a, __shfl_xor_sync(0xffffffffu, mx_a, 2));
            mx_b = fmaxf(mx_b, __shfl_xor_sync(0xffffffffu, mx_b, 1));
            mx_b = fmaxf(mx_b, __shfl_xor_sync(0xffffffffu, mx_b, 2));
            float nm_a = fmaxf(m_a, mx_a), nm_b = fmaxf(m_b, mx_b);
            float al_a = __expf(m_a - nm_a), al_b = __expf(m_b - nm_b);
            m_a = nm_a; m_b = nm_b;

            float sum_a = 0.f, sum_b = 0.f;
#pragma unroll
            for (int j = 0; j < 8; j++) {
                float p0 = __expf(s[j][0] - m_a);
                float p1 = __expf(s[j][1] - m_a);
                float p2 = __expf(s[j][2] - m_b);
                float p3 = __expf(s[j][3] - m_b);
                sum_a += p0 + p1;
                sum_b += p2 + p3;
                o[j][0] *= al_a; o[j][1] *= al_a;
                o[j][2] *= al_b; o[j][3] *= al_b;
                float2 pa = make_float2(tf32r(p0), tf32r(p1));
                float2 pb = make_float2(tf32r(p2), tf32r(p3));
                *reinterpret_cast<float2*>(&Ps[(w * 16 + g) * PS_STR + j * 8 + 2 * t4]) = pa;
                *reinterpret_cast<float2*>(&Ps[(w * 16 + g + 8) * PS_STR + j * 8 + 2 * t4]) = pb;
            }
            sum_a += __shfl_xor_sync(0xffffffffu, sum_a, 1);
            sum_a += __shfl_xor_sync(0xffffffffu, sum_a, 2);
            sum_b += __shfl_xor_sync(0xffffffffu, sum_b, 1);
            sum_b += __shfl_xor_sync(0xffffffffu, sum_b, 2);
            l_a = l_a * al_a + sum_a;
            l_b = l_b * al_b + sum_b;
            __syncwarp();

            // O += P V
#pragma unroll
            for (int kc = 0; kc < 8; kc++) {
                uint32_t pa[4];
                int pr = (w * 16 + g) * PS_STR + kc * 8 + t4;
                pa[0] = __float_as_uint(Ps[pr]);
                pa[1] = __float_as_uint(Ps[pr + 8 * PS_STR]);
                pa[2] = __float_as_uint(Ps[pr + 4]);
                pa[3] = __float_as_uint(Ps[pr + 8 * PS_STR + 4]);
#pragma unroll
                for (int j = 0; j < 8; j++) {
                    int vb = (kc * 8 + t4) * V_STR + j * 8 + g;
                    uint32_t b0 = __float_as_uint(Vs[vb]);
                    uint32_t b1 = __float_as_uint(Vs[vb + 4 * V_STR]);
                    mma_tf32(o[j], pa, b0, b1);
                }
            }
        }
        __syncthreads();
    }

    // epilogue
    float ia = 1.0f / l_a, ib = 1.0f / l_b;
#pragma unroll
    for (int j = 0; j < 8; j++) {
        int c = h * D_K + j * 8 + 2 * t4;
        float2 v0 = make_float2(o[j][0] * ia, o[j][1] * ia);
        float2 v1 = make_float2(o[j][2] * ib, o[j][3] * ib);
        *reinterpret_cast<float2*>(&O[(size_t)(wrow + g) * D_MODEL + c]) = v0;
        *reinterpret_cast<float2*>(&O[(size_t)(wrow + g + 8) * D_MODEL + c]) = v1;
    }
}

// ---------------- launcher ----------------
extern "C" void kernel_launch(void* const* d_in, const int* in_sizes, int n_in,
                              void* d_out, int out_size) {
    const float* x  = (const float*)d_in[0];
    const float* Wq = (const float*)d_in[1];
    const float* Wk = (const float*)d_in[2];
    const float* Wv = (const float*)d_in[3];
    const float* Wo = (const float*)d_in[4];
    const int*  pos = (const int*)d_in[5];
    float* out = (float*)d_out;

    float *Qp, *Kp, *Vp, *Ap;
    cudaGetSymbolAddress((void**)&Qp, g_Q);
    cudaGetSymbolAddress((void**)&Kp, g_K);
    cudaGetSymbolAddress((void**)&Vp, g_V);
    cudaGetSymbolAddress((void**)&Ap, g_AT);

    dim3 ggrid(D_MODEL / GBN, S_LEN / GBM);   // (8, 32)
    gemm3x_kernel<<<ggrid, 256>>>(x, Wq, Qp, S_LEN, D_MODEL, D_MODEL);
    gemm3x_kernel<<<ggrid, 256>>>(x, Wk, Kp, S_LEN, D_MODEL, D_MODEL);
    gemm3x_kernel<<<ggrid, 256>>>(x, Wv, Vp, S_LEN, D_MODEL, D_MODEL);

    int rope_threads = S_LEN * NUM_HEADS * (D_K / 2);
    rope_kernel<<<(rope_threads + 255) / 256, 256>>>(Qp, Kp, pos);

    cudaFuncSetAttribute(attn_mma_kernel, cudaFuncAttributeMaxDynamicSharedMemorySize, ATTN_SMEM);
    dim3 agrid(S_LEN / AQ, NUM_HEADS);        // (32, 16)
    attn_mma_kernel<<<agrid, 256, ATTN_SMEM>>>(Qp, Kp, Vp, Ap);

    gemm3x_kernel<<<ggrid, 256>>>(Ap, Wo, out, S_LEN, D_MODEL, D_MODEL);
}